// round 10
// baseline (speedup 1.0000x reference)
#include <cuda_runtime.h>
#include <cuda_fp16.h>
#include <cstdint>
#include <math.h>

#define BATCH 8
#define CIN   512
#define COUT  512
#define WDIM  512
#define INS   64
#define Y1S   66
#define PLANE 4356
#define UPS   138
#define OUTS  64
#define KTOT  4608
#define XPH   68
#define XPW   72
#define XPL   (XPH*XPW)   // 4896

__device__ float    g_styles[BATCH*CIN];
__device__ float    g_filter[12];
__device__ __half   g_wh[COUT*KTOT];
__device__ float    g_d[BATCH*COUT];
__device__ float    g_y1[BATCH*COUT*PLANE];
__device__ uint32_t g_xhl[BATCH*CIN*XPL];   // per pixel: (lo16<<16)|hi16

// ---------------- PTX helpers (sm_80-baseline only) ----------------
__device__ __forceinline__ uint32_t smem_u32(const void* p) {
    uint32_t a;
    asm("{ .reg .u64 t; cvta.to.shared.u64 t, %1; cvt.u32.u64 %0, t; }" : "=r"(a) : "l"(p));
    return a;
}
#define CP16(dst, src) \
    asm volatile("cp.async.cg.shared.global [%0], [%1], 16;" :: "r"(dst), "l"(src))
#define CPC() asm volatile("cp.async.commit_group;")
#define LDSM4(R, ad) \
    asm volatile("ldmatrix.sync.aligned.m8n8.x4.shared.b16 {%0,%1,%2,%3}, [%4];" \
        : "=r"((R)[0]), "=r"((R)[1]), "=r"((R)[2]), "=r"((R)[3]) : "r"(ad))
#define LDSM4T(R, ad) \
    asm volatile("ldmatrix.sync.aligned.m8n8.x4.trans.shared.b16 {%0,%1,%2,%3}, [%4];" \
        : "=r"((R)[0]), "=r"((R)[1]), "=r"((R)[2]), "=r"((R)[3]) : "r"(ad))
#define MMA(d, a, b0, b1) \
    asm volatile("mma.sync.aligned.m16n8k16.row.col.f32.f16.f16.f32 " \
        "{%0,%1,%2,%3}, {%4,%5,%6,%7}, {%8,%9}, {%0,%1,%2,%3};" \
        : "+f"((d)[0]), "+f"((d)[1]), "+f"((d)[2]), "+f"((d)[3]) \
        : "r"((a)[0]), "r"((a)[1]), "r"((a)[2]), "r"((a)[3]), "r"(b0), "r"(b1))

// atom(32px) -> plane pixel map; atoms 0..136 real. For a%33!=32 and a<136 the
// 32 pixels of an atom are CONTIGUOUS in the plane row (coalesced loads).
__device__ __forceinline__ bool atom_pix(int a, int j, int& P, int& Q) {
    if (a >= 137) return false;
    if (a < 132) {
        int blk = a / 33, ww = a - blk * 33;
        if (ww < 32) { P = blk*16 + (ww>>1); Q = ((ww&1)<<5) + j; return true; }
        P = blk*16 + (j>>1); Q = 64 + (j&1); return true;
    }
    if (a < 136) { int ww = a - 132; P = 64 + (ww>>1); Q = ((ww&1)<<5) + j; return true; }
    P = 64 + (j>>1); Q = 64 + (j&1); return (j < 4);
}
__device__ double bessel_i0(double x) {
    double t = x*x*0.25, term = 1.0, s = 1.0;
    for (int k = 1; k < 64; k++) { term *= t/((double)k*(double)k); s += term; if (term < 1e-18*s) break; }
    return s;
}
__device__ __forceinline__ void split2(float v, __half& h, __half& l) {
    h = __float2half_rn(v);
    l = __float2half_rn(v - __half2float(h));
}

// ============ K0: filter + styles + global style norm ============
__global__ void k0_styles(const float* __restrict__ w, const float* __restrict__ A,
                          const float* __restrict__ bias) {
    int i = threadIdx.x;
    if (i == 0) {
        const double PI = 3.14159265358979323846;
        double a = 2.285*11.0*PI*0.5 + 7.95;
        double beta = (a > 50.0) ? 0.1102*(a-8.7)
                     : (a > 21.0) ? 0.5842*pow(a-21.0,0.4)+0.07886*(a-21.0) : 0.0;
        double i0b = bessel_i0(beta), h[12], sum = 0.0;
        for (int n = 0; n < 12; n++) {
            double m = n - 5.5, sx = 0.5*m;
            double sinc = (sx==0.0) ? 1.0 : sin(PI*sx)/(PI*sx);
            double rt = m/5.5;
            h[n] = 0.5*sinc*bessel_i0(beta*sqrt(fmax(0.0,1.0-rt*rt)))/i0b;
            sum += h[n];
        }
        for (int n = 0; n < 12; n++) g_filter[n] = (float)(h[n]/sum);
    }
    float acc[BATCH];
#pragma unroll
    for (int b = 0; b < BATCH; b++) acc[b] = 0.f;
    const float* Ai = A + (size_t)i*WDIM;
    for (int k = 0; k < WDIM; k++) {
        float av = Ai[k];
#pragma unroll
        for (int b = 0; b < BATCH; b++) acc[b] += w[b*WDIM+k]*av;
    }
    float bi = bias[i], p = 0.f;
#pragma unroll
    for (int b = 0; b < BATCH; b++) { acc[b] = acc[b]*0.04419417382415922f + bi; p += acc[b]*acc[b]; }
    __shared__ float red[512];
    red[i] = p; __syncthreads();
    for (int s = 256; s > 0; s >>= 1) { if (i < s) red[i] += red[i+s]; __syncthreads(); }
    float sc = rsqrtf(red[0]*(1.0f/(BATCH*CIN)));
#pragma unroll
    for (int b = 0; b < BATCH; b++) g_styles[b*CIN+i] = acc[b]*sc;
}

// ============ K1: weight norm + fp16 (hi only) + demod ============
__global__ void k1_wnorm(const float* __restrict__ cw) {
    int o = blockIdx.x, tid = threadIdx.x;
    const float* wo = cw + (size_t)o*(CIN*9);
    __shared__ float red[256];
    float ss = 0.f;
    for (int t = tid; t < CIN*9; t += 256) { float v = wo[t]; ss += v*v; }
    red[tid] = ss; __syncthreads();
    for (int s = 128; s > 0; s >>= 1) { if (tid < s) red[tid] += red[tid+s]; __syncthreads(); }
    float r = rsqrtf(red[0]*(1.0f/(CIN*9)));
    __syncthreads();
    for (int t = tid; t < CIN*9; t += 256) {
        int i = t/9, kk = t - i*9;
        g_wh[(size_t)o*KTOT + kk*512 + i] = __float2half_rn(wo[t]*r);
    }
    float r2 = r*r;
    float part[BATCH];
#pragma unroll
    for (int b = 0; b < BATCH; b++) part[b] = 0.f;
    for (int i = tid; i < CIN; i += 256) {
        float s9 = 0.f;
#pragma unroll
        for (int k = 0; k < 9; k++) { float v = wo[i*9+k]; s9 += v*v; }
        float w2 = s9*r2;
#pragma unroll
        for (int b = 0; b < BATCH; b++) {
            float sv = g_styles[b*CIN+i];
            part[b] += sv*sv*w2;
        }
    }
#pragma unroll
    for (int b = 0; b < BATCH; b++) {
        red[tid] = part[b]; __syncthreads();
        for (int s = 128; s > 0; s >>= 1) { if (tid < s) red[tid] += red[tid+s]; __syncthreads(); }
        if (tid == 0) g_d[b*COUT+o] = rsqrtf(red[0] + 1e-8f);
        __syncthreads();
    }
}

// ============ K_pad: padded style-scaled packed fp16-split input ============
__global__ void k_pad(const float* __restrict__ x) {
    int idx = blockIdx.x*256 + threadIdx.x;
    if (idx >= BATCH*CIN*XPL) return;
    int col = idx % XPW, row = (idx/XPW) % XPH;
    int c = (idx/XPL) % CIN, b = idx/(XPL*CIN);
    int ri = row - 2, ci = col - 2;
    float v = 0.f;
    if (ri >= 0 && ri < INS && ci >= 0 && ci < INS)
        v = x[(((size_t)b*CIN+c)*INS+ri)*INS+ci] * g_styles[b*CIN+c];
    __half h, l; split2(v, h, l);
    g_xhl[idx] = ((uint32_t)__half_as_ushort(l) << 16) | (uint32_t)__half_as_ushort(h);
}

// ============ K_gemm: HMMA (wh)x(xh+xl), K-chunk=64, 2-stage ============
// SMEM halfs per stage: A[128][72]=9216 | Bh[64][136]=8704 | Bl 8704
#define SB_H 9216
#define STGH 26624                     // halfs per stage
#define GEMM_SMEM (2*STGH*2)           // 106496 bytes
#define NCH 72

__global__ __launch_bounds__(256, 2)
void k_gemm(const float* __restrict__ cbias) {
    extern __shared__ __align__(16) char smraw[];
    uint32_t sb = smem_u32(smraw);
    int tid = threadIdx.x, w = tid >> 5, lane = tid & 31;
    int nt = blockIdx.x, oc0 = blockIdx.y * 128, bz = blockIdx.z;
    int wm = w & 1, wn = w >> 1;
    int m0 = wm * 64, n0 = wn * 32;

    // ---- B geometry: warp w loads channels [8w,8w+8) x atoms 0..3 ----
    int pofs[4]; unsigned pv = 0;
#pragma unroll
    for (int t = 0; t < 4; t++) {
        int P, Q;
        if (atom_pix(nt*4 + t, lane, P, Q)) { pofs[t] = P*XPW + Q; pv |= (1u << t); }
        else pofs[t] = 0;
    }

    // ---- A geometry: thread t loads row t>>1, half t&1 (4x CP16 = 64B) ----
    int arow = tid >> 1, ahalf = tid & 1;

    // ---- ldmatrix base offsets (bytes from stage base) ----
    uint32_t a_base = (uint32_t)(((m0 + (lane & 15))*72 + ((lane >> 4)*8)) * 2);
    uint32_t b_base = (uint32_t)((SB_H + ((lane & 7) + ((lane >> 3) & 1)*8)*136
                                  + n0 + ((lane >> 4)*8)) * 2);

    float acc[64];
#pragma unroll
    for (int t = 0; t < 64; t++) acc[t] = 0.f;

    uint32_t breg[16];

    auto loadA = [&](int ch, int st) {  // cp.async, 16B aligned everywhere
        const __half* src = g_wh + (size_t)(oc0 + arow)*KTOT + ch*64 + ahalf*32;
        uint32_t dst = sb + (uint32_t)((st*STGH + arow*72 + ahalf*32) * 2);
        CP16(dst,      src);
        CP16(dst + 16, src + 8);
        CP16(dst + 32, src + 16);
        CP16(dst + 48, src + 24);
    };
    // half p of the B gather: channels [8w+4p, 8w+4p+4) x atoms 0..3
    auto ldgB = [&](int ch, int p) {
        int tap = ch >> 3, ic0 = (ch & 7) << 6;
        int sh = (tap/3)*XPW + (tap - (tap/3)*3);
        const uint32_t* xs = g_xhl + (size_t)bz*(CIN*XPL)
                           + (size_t)(ic0 + w*8 + p*4)*XPL + sh;
#pragma unroll
        for (int i = 0; i < 16; i++) {
            int k = i >> 2, a = i & 3;
            breg[i] = ((pv >> a) & 1u) ? __ldg(xs + (size_t)k*XPL + pofs[a]) : 0u;
        }
    };
    auto stsB = [&](int st, int p) {
        uint32_t base = (uint32_t)((st*STGH + SB_H) * 2);
#pragma unroll
        for (int i = 0; i < 16; i++) {
            int k = (w << 3) + (p << 2) + (i >> 2), a = i & 3;
            uint32_t idx = (uint32_t)((k*136 + a*32 + lane) * 2);
            *(unsigned short*)(smraw + base + idx)         = (unsigned short)(breg[i] & 0xFFFF);
            *(unsigned short*)(smraw + base + 17408 + idx) = (unsigned short)(breg[i] >> 16);
        }
    };
    auto compute = [&](uint32_t sbase, int k16) {
        uint32_t sA = sbase + a_base + k16*32;
        uint32_t sB = sbase + b_base + k16*4352;
        uint32_t ah[16], bh[8], bl[8];
#pragma unroll
        for (int mt = 0; mt < 4; mt++) LDSM4(&ah[mt*4], sA + mt*2304);
#pragma unroll
        for (int n2 = 0; n2 < 2; n2++) LDSM4T(&bh[n2*4], sB + n2*32);
#pragma unroll
        for (int mt = 0; mt < 4; mt++)
#pragma unroll
            for (int n = 0; n < 4; n++)
                MMA(&acc[(mt*4+n)*4], &ah[mt*4],
                    bh[(n>>1)*4 + (n&1)*2], bh[(n>>1)*4 + (n&1)*2 + 1]);
#pragma unroll
        for (int n2 = 0; n2 < 2; n2++) LDSM4T(&bl[n2*4], sB + 17408 + n2*32);
#pragma unroll
        for (int mt = 0; mt < 4; mt++)
#pragma unroll
            for (int n = 0; n < 4; n++)
                MMA(&acc[(mt*4+n)*4], &ah[mt*4],
                    bl[(n>>1)*4 + (n&1)*2], bl[(n>>1)*4 + (n&1)*2 + 1]);
    };

    // prologue: fill stage 0
    ldgB(0, 0); stsB(0, 0);
    ldgB(0, 1); stsB(0, 1);
    loadA(0, 0); CPC();
    asm volatile("cp.async.wait_group 0;");
    __syncthreads();

    for (int ch = 0; ch < NCH; ch++) {
        int st = ch & 1;
        bool nxt = (ch + 1 < NCH);
        if (nxt) {
            loadA(ch + 1, st ^ 1); CPC();
            ldgB(ch + 1, 0);
        }
        uint32_t sbase = sb + (uint32_t)(st * STGH * 2);
        compute(sbase, 0);
        compute(sbase, 1);
        if (nxt) {
            stsB(st ^ 1, 0);
            ldgB(ch + 1, 1);
        }
        compute(sbase, 2);
        compute(sbase, 3);
        if (nxt) {
            asm volatile("cp.async.wait_group 0;");
            stsB(st ^ 1, 1);
        }
        __syncthreads();
    }

    // ---- epilogue: demod + bias, float2 stores ----
#pragma unroll
    for (int mt = 0; mt < 4; mt++) {
        int ocA = oc0 + m0 + mt*16 + (lane >> 2);
        float dmA = g_d[bz*COUT + ocA],     biA = cbias[ocA];
        float dmB = g_d[bz*COUT + ocA + 8], biB = cbias[ocA + 8];
        size_t rowA = ((size_t)(bz*COUT + ocA)) * PLANE;
        size_t rowB = rowA + (size_t)8 * PLANE;
#pragma unroll
        for (int n = 0; n < 4; n++) {
            int nl = n0 + n*8 + (lane & 3)*2;
            int P, Q;
            if (!atom_pix(nt*4 + (nl >> 5), nl & 31, P, Q)) continue;
            int po = P*Y1S + Q;
            float* c = &acc[(mt*4+n)*4];
            *(float2*)(g_y1 + rowA + po) = make_float2(c[0]*dmA + biA, c[1]*dmA + biA);
            *(float2*)(g_y1 + rowB + po) = make_float2(c[2]*dmB + biB, c[3]*dmB + biB);
        }
    }
}

// ============ K4: fused upFIR -> lrelu/clamp -> downFIR (fp16 act) ============
// smem: vt 9108 f32 (36432B) | act 138x139 f16 (38364B) => 74796B, 3 CTAs/SM
#define K4_VT_BYTES  (9108*4)
#define K4_SMEM      (K4_VT_BYTES + 19182*2)
#define UTAPC(T, FI, LOADEXPR) { int n = rr + (T) - 9; if (n >= 0 && n < 132) { int jph = n >> 1; acc += (LOADEXPR)*fl[FI]; } }

__global__ __launch_bounds__(512, 3)
void k4_fir(float* __restrict__ out) {
    int plane = blockIdx.x, tid = threadIdx.x;
    extern __shared__ char sm4[];
    float*  vt  = (float*)sm4;
    __half* act = (__half*)(sm4 + K4_VT_BYTES);
    const float* src = g_y1 + (size_t)plane*PLANE;
    float fl[12];
#pragma unroll
    for (int k = 0; k < 12; k++) fl[k] = g_filter[k];

    // vertical up-FIR (polyphase, gain 4): vt[138][66]
    for (int e = tid; e < UPS*Y1S; e += 512) {
        int rr = e/Y1S, i = e - rr*Y1S;
        float acc = 0.f;
        if ((rr & 1) == 0) {
            UTAPC(1,10, src[jph*Y1S+i]); UTAPC(3,8, src[jph*Y1S+i]); UTAPC(5,6, src[jph*Y1S+i]);
            UTAPC(7,4, src[jph*Y1S+i]); UTAPC(9,2, src[jph*Y1S+i]); UTAPC(11,0, src[jph*Y1S+i]);
        } else {
            UTAPC(0,11, src[jph*Y1S+i]); UTAPC(2,9, src[jph*Y1S+i]); UTAPC(4,7, src[jph*Y1S+i]);
            UTAPC(6,5, src[jph*Y1S+i]); UTAPC(8,3, src[jph*Y1S+i]); UTAPC(10,1, src[jph*Y1S+i]);
        }
        vt[e] = 4.f*acc;
    }
    __syncthreads();
    // horizontal up-FIR + lrelu*sqrt2 + clamp: act[138][139] fp16
    for (int e = tid; e < UPS*UPS; e += 512) {
        int r = e/UPS, rr = e - r*UPS;
        const float* vr = vt + r*Y1S;
        float acc = 0.f;
        if ((rr & 1) == 0) {
            UTAPC(1,10, vr[jph]); UTAPC(3,8, vr[jph]); UTAPC(5,6, vr[jph]);
            UTAPC(7,4, vr[jph]); UTAPC(9,2, vr[jph]); UTAPC(11,0, vr[jph]);
        } else {
            UTAPC(0,11, vr[jph]); UTAPC(2,9, vr[jph]); UTAPC(4,7, vr[jph]);
            UTAPC(6,5, vr[jph]); UTAPC(8,3, vr[jph]); UTAPC(10,1, vr[jph]);
        }
        float a = (acc >= 0.f ? acc : 0.2f*acc)*1.4142135623730951f;
        act[r*139 + rr] = __float2half_rn(fminf(fmaxf(a, -256.f), 256.f));
    }
    __syncthreads();
    // vertical down-FIR (stride 2): reuse vt as [64][138]
    for (int e = tid; e < OUTS*UPS; e += 512) {
        int rr = e/UPS, j = e - rr*UPS;
        const __half* ap = act + (2*rr)*139 + j;
        float acc = 0.f;
#pragma unroll
        for (int t = 0; t < 12; t++) acc += fl[11-t]*__half2float(ap[t*139]);
        vt[rr*UPS + j] = acc;
    }
    __syncthreads();
    // horizontal down-FIR (stride 2) -> out
    float* dst = out + (size_t)plane*(OUTS*OUTS);
    for (int e = tid; e < OUTS*OUTS; e += 512) {
        int rr = e/OUTS, cc = e - rr*OUTS;
        const float* dp = vt + rr*UPS + 2*cc;
        float acc = 0.f;
#pragma unroll
        for (int t = 0; t < 12; t++) acc += fl[11-t]*dp[t];
        dst[rr*OUTS + cc] = acc;
    }
}

// ============ launch ============
extern "C" void kernel_launch(void* const* d_in, const int* in_sizes, int n_in,
                              void* d_out, int out_size) {
    const float* x  = (const float*)d_in[0];
    const float* w  = (const float*)d_in[1];
    const float* A  = (const float*)d_in[2];
    const float* ab = (const float*)d_in[3];
    const float* cw = (const float*)d_in[4];
    const float* cb = (const float*)d_in[5];
    float* out = (float*)d_out;

    cudaFuncSetAttribute(k_gemm, cudaFuncAttributeMaxDynamicSharedMemorySize, GEMM_SMEM);
    cudaFuncSetAttribute(k4_fir, cudaFuncAttributeMaxDynamicSharedMemorySize, K4_SMEM);

    k0_styles<<<1, 512>>>(w, A, ab);
    k1_wnorm<<<COUT, 256>>>(cw);
    k_pad<<<(BATCH*CIN*XPL + 255)/256, 256>>>(x);
    k_gemm<<<dim3(35, 4, BATCH), 256, GEMM_SMEM>>>(cb);   // launch idx 3
    k4_fir<<<BATCH*COUT, 512, K4_SMEM>>>(out);
}

// round 11
// speedup vs baseline: 1.2460x; 1.2460x over previous
#include <cuda_runtime.h>
#include <cuda_fp16.h>
#include <cstdint>
#include <math.h>

#define BATCH 8
#define CIN   512
#define COUT  512
#define WDIM  512
#define INS   64
#define Y1S   66
#define PLANE 4356
#define UPS   138
#define OUTS  64
#define KTOT  4608
#define XPH   68
#define XPW   72
#define XPL   (XPH*XPW)   // 4896

__device__ float    g_styles[BATCH*CIN];
__device__ float    g_filter[12];
__device__ __half   g_wh[COUT*KTOT];
__device__ float    g_d[BATCH*COUT];
__device__ float    g_y1[BATCH*COUT*PLANE];
__device__ __half   g_xh[BATCH*CIN*XPL];

// ---------------- PTX helpers (sm_80-baseline only) ----------------
__device__ __forceinline__ uint32_t smem_u32(const void* p) {
    uint32_t a;
    asm("{ .reg .u64 t; cvta.to.shared.u64 t, %1; cvt.u32.u64 %0, t; }" : "=r"(a) : "l"(p));
    return a;
}
#define CP16(dst, src) \
    asm volatile("cp.async.cg.shared.global [%0], [%1], 16;" :: "r"(dst), "l"(src))
#define CPC() asm volatile("cp.async.commit_group;")
#define LDSM4(R, ad) \
    asm volatile("ldmatrix.sync.aligned.m8n8.x4.shared.b16 {%0,%1,%2,%3}, [%4];" \
        : "=r"((R)[0]), "=r"((R)[1]), "=r"((R)[2]), "=r"((R)[3]) : "r"(ad))
#define LDSM4T(R, ad) \
    asm volatile("ldmatrix.sync.aligned.m8n8.x4.trans.shared.b16 {%0,%1,%2,%3}, [%4];" \
        : "=r"((R)[0]), "=r"((R)[1]), "=r"((R)[2]), "=r"((R)[3]) : "r"(ad))
#define MMA(d, a, b0, b1) \
    asm volatile("mma.sync.aligned.m16n8k16.row.col.f32.f16.f16.f32 " \
        "{%0,%1,%2,%3}, {%4,%5,%6,%7}, {%8,%9}, {%0,%1,%2,%3};" \
        : "+f"((d)[0]), "+f"((d)[1]), "+f"((d)[2]), "+f"((d)[3]) \
        : "r"((a)[0]), "r"((a)[1]), "r"((a)[2]), "r"((a)[3]), "r"(b0), "r"(b1))

// atom(32px) -> plane pixel map; atoms 0..136 real. For a%33!=32 and a<136 the
// 32 pixels of an atom are CONTIGUOUS in the plane row (coalesced loads).
__device__ __forceinline__ bool atom_pix(int a, int j, int& P, int& Q) {
    if (a >= 137) return false;
    if (a < 132) {
        int blk = a / 33, ww = a - blk * 33;
        if (ww < 32) { P = blk*16 + (ww>>1); Q = ((ww&1)<<5) + j; return true; }
        P = blk*16 + (j>>1); Q = 64 + (j&1); return true;
    }
    if (a < 136) { int ww = a - 132; P = 64 + (ww>>1); Q = ((ww&1)<<5) + j; return true; }
    P = 64 + (j>>1); Q = 64 + (j&1); return (j < 4);
}
__device__ double bessel_i0(double x) {
    double t = x*x*0.25, term = 1.0, s = 1.0;
    for (int k = 1; k < 64; k++) { term *= t/((double)k*(double)k); s += term; if (term < 1e-18*s) break; }
    return s;
}

// ============ K0: filter + styles + global style norm ============
__global__ void k0_styles(const float* __restrict__ w, const float* __restrict__ A,
                          const float* __restrict__ bias) {
    int i = threadIdx.x;
    if (i == 0) {
        const double PI = 3.14159265358979323846;
        double a = 2.285*11.0*PI*0.5 + 7.95;
        double beta = (a > 50.0) ? 0.1102*(a-8.7)
                     : (a > 21.0) ? 0.5842*pow(a-21.0,0.4)+0.07886*(a-21.0) : 0.0;
        double i0b = bessel_i0(beta), h[12], sum = 0.0;
        for (int n = 0; n < 12; n++) {
            double m = n - 5.5, sx = 0.5*m;
            double sinc = (sx==0.0) ? 1.0 : sin(PI*sx)/(PI*sx);
            double rt = m/5.5;
            h[n] = 0.5*sinc*bessel_i0(beta*sqrt(fmax(0.0,1.0-rt*rt)))/i0b;
            sum += h[n];
        }
        for (int n = 0; n < 12; n++) g_filter[n] = (float)(h[n]/sum);
    }
    float acc[BATCH];
#pragma unroll
    for (int b = 0; b < BATCH; b++) acc[b] = 0.f;
    const float* Ai = A + (size_t)i*WDIM;
    for (int k = 0; k < WDIM; k++) {
        float av = Ai[k];
#pragma unroll
        for (int b = 0; b < BATCH; b++) acc[b] += w[b*WDIM+k]*av;
    }
    float bi = bias[i], p = 0.f;
#pragma unroll
    for (int b = 0; b < BATCH; b++) { acc[b] = acc[b]*0.04419417382415922f + bi; p += acc[b]*acc[b]; }
    __shared__ float red[512];
    red[i] = p; __syncthreads();
    for (int s = 256; s > 0; s >>= 1) { if (i < s) red[i] += red[i+s]; __syncthreads(); }
    float sc = rsqrtf(red[0]*(1.0f/(BATCH*CIN)));
#pragma unroll
    for (int b = 0; b < BATCH; b++) g_styles[b*CIN+i] = acc[b]*sc;
}

// ============ K1: weight norm + fp16 + demod ============
__global__ void k1_wnorm(const float* __restrict__ cw) {
    int o = blockIdx.x, tid = threadIdx.x;
    const float* wo = cw + (size_t)o*(CIN*9);
    __shared__ float red[256];
    float ss = 0.f;
    for (int t = tid; t < CIN*9; t += 256) { float v = wo[t]; ss += v*v; }
    red[tid] = ss; __syncthreads();
    for (int s = 128; s > 0; s >>= 1) { if (tid < s) red[tid] += red[tid+s]; __syncthreads(); }
    float r = rsqrtf(red[0]*(1.0f/(CIN*9)));
    __syncthreads();
    for (int t = tid; t < CIN*9; t += 256) {
        int i = t/9, kk = t - i*9;
        g_wh[(size_t)o*KTOT + kk*512 + i] = __float2half_rn(wo[t]*r);
    }
    float r2 = r*r;
    float part[BATCH];
#pragma unroll
    for (int b = 0; b < BATCH; b++) part[b] = 0.f;
    for (int i = tid; i < CIN; i += 256) {
        float s9 = 0.f;
#pragma unroll
        for (int k = 0; k < 9; k++) { float v = wo[i*9+k]; s9 += v*v; }
        float w2 = s9*r2;
#pragma unroll
        for (int b = 0; b < BATCH; b++) {
            float sv = g_styles[b*CIN+i];
            part[b] += sv*sv*w2;
        }
    }
#pragma unroll
    for (int b = 0; b < BATCH; b++) {
        red[tid] = part[b]; __syncthreads();
        for (int s = 128; s > 0; s >>= 1) { if (tid < s) red[tid] += red[tid+s]; __syncthreads(); }
        if (tid == 0) g_d[b*COUT+o] = rsqrtf(red[0] + 1e-8f);
        __syncthreads();
    }
}

// ============ K_pad: padded style-scaled fp16 input ============
__global__ void k_pad(const float* __restrict__ x) {
    int idx = blockIdx.x*256 + threadIdx.x;
    if (idx >= BATCH*CIN*XPL) return;
    int col = idx % XPW, row = (idx/XPW) % XPH;
    int c = (idx/XPL) % CIN, b = idx/(XPL*CIN);
    int ri = row - 2, ci = col - 2;
    float v = 0.f;
    if (ri >= 0 && ri < INS && ci >= 0 && ci < INS)
        v = x[(((size_t)b*CIN+c)*INS+ri)*INS+ci] * g_styles[b*CIN+c];
    g_xh[idx] = __float2half_rn(v);
}

// ============ K_gemm: HMMA single-term fp16 implicit conv ============
// SMEM halfs per stage: A[128][40]=5120 | B[32][136]=4352
#define SB_H 5120
#define STGH 9472                      // halfs per stage
#define GEMM_SMEM (2*STGH*2)           // 37888 bytes
#define NCH 144

__global__ __launch_bounds__(256, 2)
void k_gemm(const float* __restrict__ cbias) {
    extern __shared__ __align__(16) char smraw[];
    uint32_t sb = smem_u32(smraw);
    int tid = threadIdx.x, w = tid >> 5, lane = tid & 31;
    int nt = blockIdx.x, oc0 = blockIdx.y * 128, bz = blockIdx.z;
    int wm = w & 1, wn = w >> 1;
    int m0 = wm * 64, n0 = wn * 32;

    // ---- B geometry: warp w loads channels [4w,4w+4) x atoms 0..3 ----
    int pofs[4]; unsigned pv = 0;
#pragma unroll
    for (int t = 0; t < 4; t++) {
        int P, Q;
        if (atom_pix(nt*4 + t, lane, P, Q)) { pofs[t] = P*XPW + Q; pv |= (1u << t); }
        else pofs[t] = 0;
    }

    // ---- A geometry: thread t loads row t>>1, half t&1 (2x CP16) ----
    int arow = tid >> 1, ahalf = tid & 1;

    // ---- ldmatrix base offsets (bytes from stage base) ----
    uint32_t a_base = (uint32_t)(((m0 + (lane & 15))*40 + ((lane >> 4)*8)) * 2);
    uint32_t b_base = (uint32_t)((SB_H + ((lane & 7) + ((lane >> 3) & 1)*8)*136
                                  + n0 + ((lane >> 4)*8)) * 2);

    float acc[64];
#pragma unroll
    for (int t = 0; t < 64; t++) acc[t] = 0.f;

    unsigned short breg[16];

    auto loadA = [&](int ch, int st) {  // cp.async, 16B aligned everywhere
        const __half* src = g_wh + (size_t)(oc0 + arow)*KTOT + ch*32 + ahalf*16;
        uint32_t dst = sb + (uint32_t)((st*STGH + arow*40 + ahalf*16) * 2);
        CP16(dst,      src);
        CP16(dst + 16, src + 8);
    };
    auto ldgB = [&](int ch) {           // coalesced u16 LDG per (channel,atom) row
        int tap = ch >> 4, icb = (ch & 15) << 5;
        int sh = (tap/3)*XPW + (tap - (tap/3)*3);
        const __half* xs = g_xh + (size_t)bz*(CIN*XPL) + (size_t)(icb + w*4)*XPL + sh;
#pragma unroll
        for (int i = 0; i < 16; i++) {
            int k = i >> 2, a = i & 3;   // channel w*4+k, atom a
            breg[i] = ((pv >> a) & 1u)
                ? __ldg((const unsigned short*)xs + (size_t)k*XPL + pofs[a]) : 0;
        }
    };
    auto stsB = [&](int st) {
        uint32_t base = (uint32_t)((st*STGH + SB_H) * 2);
#pragma unroll
        for (int i = 0; i < 16; i++) {
            int k = (w << 2) + (i >> 2), a = i & 3;
            uint32_t idx = (uint32_t)((k*136 + a*32 + lane) * 2);
            *(unsigned short*)(smraw + base + idx) = breg[i];
        }
    };

    // prologue: fill stage 0
    ldgB(0);
    stsB(0);
    loadA(0, 0); CPC();
    asm volatile("cp.async.wait_group 0;");
    __syncthreads();

    for (int ch = 0; ch < NCH; ch++) {
        int st = ch & 1;
        if (ch + 1 < NCH) {
            ldgB(ch + 1);
            loadA(ch + 1, st ^ 1); CPC();
        }

        uint32_t sbase = sb + (uint32_t)(st * STGH * 2);
#pragma unroll
        for (int k16 = 0; k16 < 2; k16++) {
            uint32_t sA = sbase + a_base + k16*32;
            uint32_t sB = sbase + b_base + k16*(16*136*2);
            uint32_t ah[16], bh[8];
#pragma unroll
            for (int mt = 0; mt < 4; mt++) LDSM4(&ah[mt*4], sA + mt*1280);
#pragma unroll
            for (int n2 = 0; n2 < 2; n2++) LDSM4T(&bh[n2*4], sB + n2*32);
#pragma unroll
            for (int mt = 0; mt < 4; mt++)
#pragma unroll
                for (int n = 0; n < 4; n++)
                    MMA(&acc[(mt*4+n)*4], &ah[mt*4],
                        bh[(n>>1)*4 + (n&1)*2], bh[(n>>1)*4 + (n&1)*2 + 1]);
        }

        if (ch + 1 < NCH) {
            asm volatile("cp.async.wait_group 0;");
            stsB(st ^ 1);
        }
        __syncthreads();
    }

    // ---- epilogue: demod + bias, float2 stores ----
#pragma unroll
    for (int mt = 0; mt < 4; mt++) {
        int ocA = oc0 + m0 + mt*16 + (lane >> 2);
        float dmA = g_d[bz*COUT + ocA],     biA = cbias[ocA];
        float dmB = g_d[bz*COUT + ocA + 8], biB = cbias[ocA + 8];
        size_t rowA = ((size_t)(bz*COUT + ocA)) * PLANE;
        size_t rowB = rowA + (size_t)8 * PLANE;
#pragma unroll
        for (int n = 0; n < 4; n++) {
            int nl = n0 + n*8 + (lane & 3)*2;
            int P, Q;
            if (!atom_pix(nt*4 + (nl >> 5), nl & 31, P, Q)) continue;
            int po = P*Y1S + Q;
            float* c = &acc[(mt*4+n)*4];
            *(float2*)(g_y1 + rowA + po) = make_float2(c[0]*dmA + biA, c[1]*dmA + biA);
            *(float2*)(g_y1 + rowB + po) = make_float2(c[2]*dmB + biB, c[3]*dmB + biB);
        }
    }
}

// ============ K4: fused upFIR -> lrelu/clamp -> downFIR (fp16 act) ============
// smem: vt 9108 f32 (36432B) | act 138x139 f16 (38364B) => 74796B, 3 CTAs/SM
#define K4_VT_BYTES  (9108*4)
#define K4_SMEM      (K4_VT_BYTES + 19182*2)
#define UTAPC(T, FI, LOADEXPR) { int n = rr + (T) - 9; if (n >= 0 && n < 132) { int jph = n >> 1; acc += (LOADEXPR)*fl[FI]; } }

__global__ __launch_bounds__(512, 3)
void k4_fir(float* __restrict__ out) {
    int plane = blockIdx.x, tid = threadIdx.x;
    extern __shared__ char sm4[];
    float*  vt  = (float*)sm4;
    __half* act = (__half*)(sm4 + K4_VT_BYTES);
    const float* src = g_y1 + (size_t)plane*PLANE;
    float fl[12];
#pragma unroll
    for (int k = 0; k < 12; k++) fl[k] = g_filter[k];

    for (int e = tid; e < UPS*Y1S; e += 512) {
        int rr = e/Y1S, i = e - rr*Y1S;
        float acc = 0.f;
        if ((rr & 1) == 0) {
            UTAPC(1,10, src[jph*Y1S+i]); UTAPC(3,8, src[jph*Y1S+i]); UTAPC(5,6, src[jph*Y1S+i]);
            UTAPC(7,4, src[jph*Y1S+i]); UTAPC(9,2, src[jph*Y1S+i]); UTAPC(11,0, src[jph*Y1S+i]);
        } else {
            UTAPC(0,11, src[jph*Y1S+i]); UTAPC(2,9, src[jph*Y1S+i]); UTAPC(4,7, src[jph*Y1S+i]);
            UTAPC(6,5, src[jph*Y1S+i]); UTAPC(8,3, src[jph*Y1S+i]); UTAPC(10,1, src[jph*Y1S+i]);
        }
        vt[e] = 4.f*acc;
    }
    __syncthreads();
    for (int e = tid; e < UPS*UPS; e += 512) {
        int r = e/UPS, rr = e - r*UPS;
        const float* vr = vt + r*Y1S;
        float acc = 0.f;
        if ((rr & 1) == 0) {
            UTAPC(1,10, vr[jph]); UTAPC(3,8, vr[jph]); UTAPC(5,6, vr[jph]);
            UTAPC(7,4, vr[jph]); UTAPC(9,2, vr[jph]); UTAPC(11,0, vr[jph]);
        } else {
            UTAPC(0,11, vr[jph]); UTAPC(2,9, vr[jph]); UTAPC(4,7, vr[jph]);
            UTAPC(6,5, vr[jph]); UTAPC(8,3, vr[jph]); UTAPC(10,1, vr[jph]);
        }
        float a = (acc >= 0.f ? acc : 0.2f*acc)*1.4142135623730951f;
        act[r*139 + rr] = __float2half_rn(fminf(fmaxf(a, -256.f), 256.f));
    }
    __syncthreads();
    for (int e = tid; e < OUTS*UPS; e += 512) {
        int rr = e/UPS, j = e - rr*UPS;
        const __half* ap = act + (2*rr)*139 + j;
        float acc = 0.f;
#pragma unroll
        for (int t = 0; t < 12; t++) acc += fl[11-t]*__half2float(ap[t*139]);
        vt[rr*UPS + j] = acc;
    }
    __syncthreads();
    float* dst = out + (size_t)plane*(OUTS*OUTS);
    for (int e = tid; e < OUTS*OUTS; e += 512) {
        int rr = e/OUTS, cc = e - rr*OUTS;
        const float* dp = vt + rr*UPS + 2*cc;
        float acc = 0.f;
#pragma unroll
        for (int t = 0; t < 12; t++) acc += fl[11-t]*dp[t];
        dst[rr*OUTS + cc] = acc;
    }
}

// ============ launch ============
extern "C" void kernel_launch(void* const* d_in, const int* in_sizes, int n_in,
                              void* d_out, int out_size) {
    const float* x  = (const float*)d_in[0];
    const float* w  = (const float*)d_in[1];
    const float* A  = (const float*)d_in[2];
    const float* ab = (const float*)d_in[3];
    const float* cw = (const float*)d_in[4];
    const float* cb = (const float*)d_in[5];
    float* out = (float*)d_out;

    cudaFuncSetAttribute(k_gemm, cudaFuncAttributeMaxDynamicSharedMemorySize, GEMM_SMEM);
    cudaFuncSetAttribute(k4_fir, cudaFuncAttributeMaxDynamicSharedMemorySize, K4_SMEM);

    k0_styles<<<1, 512>>>(w, A, ab);
    k1_wnorm<<<COUT, 256>>>(cw);
    k_pad<<<(BATCH*CIN*XPL + 255)/256, 256>>>(x);
    k_gemm<<<dim3(35, 4, BATCH), 256, GEMM_SMEM>>>(cb);   // launch idx 3
    k4_fir<<<BATCH*COUT, 512, K4_SMEM>>>(out);
}

// round 12
// speedup vs baseline: 1.5115x; 1.2130x over previous
#include <cuda_runtime.h>
#include <cuda_fp16.h>
#include <cstdint>
#include <math.h>

#define BATCH 8
#define CIN   512
#define COUT  512
#define WDIM  512
#define INS   64
#define Y1S   66
#define PLANE 4356
#define UPS   138
#define OUTS  64
#define KTOT  4608
#define XPH   68
#define XPW   72
#define XPL   (XPH*XPW)   // 4896

__device__ float    g_styles[BATCH*CIN];
__device__ float    g_filter[12];
__device__ __half   g_wh[COUT*KTOT];
__device__ float    g_d[BATCH*COUT];
__device__ float    g_y1[BATCH*COUT*PLANE];
__device__ __half   g_xh[BATCH*CIN*XPL];

// ---------------- PTX helpers (sm_80-baseline only) ----------------
__device__ __forceinline__ uint32_t smem_u32(const void* p) {
    uint32_t a;
    asm("{ .reg .u64 t; cvta.to.shared.u64 t, %1; cvt.u32.u64 %0, t; }" : "=r"(a) : "l"(p));
    return a;
}
#define CP16(dst, src) \
    asm volatile("cp.async.cg.shared.global [%0], [%1], 16;" :: "r"(dst), "l"(src))
#define CPC() asm volatile("cp.async.commit_group;")
#define LDSM4(R, ad) \
    asm volatile("ldmatrix.sync.aligned.m8n8.x4.shared.b16 {%0,%1,%2,%3}, [%4];" \
        : "=r"((R)[0]), "=r"((R)[1]), "=r"((R)[2]), "=r"((R)[3]) : "r"(ad))
#define LDSM4T(R, ad) \
    asm volatile("ldmatrix.sync.aligned.m8n8.x4.trans.shared.b16 {%0,%1,%2,%3}, [%4];" \
        : "=r"((R)[0]), "=r"((R)[1]), "=r"((R)[2]), "=r"((R)[3]) : "r"(ad))
#define MMA(d, a, b0, b1) \
    asm volatile("mma.sync.aligned.m16n8k16.row.col.f32.f16.f16.f32 " \
        "{%0,%1,%2,%3}, {%4,%5,%6,%7}, {%8,%9}, {%0,%1,%2,%3};" \
        : "+f"((d)[0]), "+f"((d)[1]), "+f"((d)[2]), "+f"((d)[3]) \
        : "r"((a)[0]), "r"((a)[1]), "r"((a)[2]), "r"((a)[3]), "r"(b0), "r"(b1))

// atom(32px) -> plane pixel map; atoms 0..136 real. For a%33!=32 and a<136 the
// 32 pixels of an atom are CONTIGUOUS in the plane row (coalesced loads).
__device__ __forceinline__ bool atom_pix(int a, int j, int& P, int& Q) {
    if (a >= 137) return false;
    if (a < 132) {
        int blk = a / 33, ww = a - blk * 33;
        if (ww < 32) { P = blk*16 + (ww>>1); Q = ((ww&1)<<5) + j; return true; }
        P = blk*16 + (j>>1); Q = 64 + (j&1); return true;
    }
    if (a < 136) { int ww = a - 132; P = 64 + (ww>>1); Q = ((ww&1)<<5) + j; return true; }
    P = 64 + (j>>1); Q = 64 + (j&1); return (j < 4);
}
__device__ double bessel_i0(double x) {
    double t = x*x*0.25, term = 1.0, s = 1.0;
    for (int k = 1; k < 64; k++) { term *= t/((double)k*(double)k); s += term; if (term < 1e-18*s) break; }
    return s;
}

// ============ K0: filter + styles + global style norm ============
__global__ void k0_styles(const float* __restrict__ w, const float* __restrict__ A,
                          const float* __restrict__ bias) {
    int i = threadIdx.x;
    if (i == 0) {
        const double PI = 3.14159265358979323846;
        double a = 2.285*11.0*PI*0.5 + 7.95;
        double beta = (a > 50.0) ? 0.1102*(a-8.7)
                     : (a > 21.0) ? 0.5842*pow(a-21.0,0.4)+0.07886*(a-21.0) : 0.0;
        double i0b = bessel_i0(beta), h[12], sum = 0.0;
        for (int n = 0; n < 12; n++) {
            double m = n - 5.5, sx = 0.5*m;
            double sinc = (sx==0.0) ? 1.0 : sin(PI*sx)/(PI*sx);
            double rt = m/5.5;
            h[n] = 0.5*sinc*bessel_i0(beta*sqrt(fmax(0.0,1.0-rt*rt)))/i0b;
            sum += h[n];
        }
        for (int n = 0; n < 12; n++) g_filter[n] = (float)(h[n]/sum);
    }
    float acc[BATCH];
#pragma unroll
    for (int b = 0; b < BATCH; b++) acc[b] = 0.f;
    const float* Ai = A + (size_t)i*WDIM;
    for (int k = 0; k < WDIM; k++) {
        float av = Ai[k];
#pragma unroll
        for (int b = 0; b < BATCH; b++) acc[b] += w[b*WDIM+k]*av;
    }
    float bi = bias[i], p = 0.f;
#pragma unroll
    for (int b = 0; b < BATCH; b++) { acc[b] = acc[b]*0.04419417382415922f + bi; p += acc[b]*acc[b]; }
    __shared__ float red[512];
    red[i] = p; __syncthreads();
    for (int s = 256; s > 0; s >>= 1) { if (i < s) red[i] += red[i+s]; __syncthreads(); }
    float sc = rsqrtf(red[0]*(1.0f/(BATCH*CIN)));
#pragma unroll
    for (int b = 0; b < BATCH; b++) g_styles[b*CIN+i] = acc[b]*sc;
}

// ============ K1: weight norm + fp16 + demod ============
__global__ void k1_wnorm(const float* __restrict__ cw) {
    int o = blockIdx.x, tid = threadIdx.x;
    const float* wo = cw + (size_t)o*(CIN*9);
    __shared__ float red[256];
    float ss = 0.f;
    for (int t = tid; t < CIN*9; t += 256) { float v = wo[t]; ss += v*v; }
    red[tid] = ss; __syncthreads();
    for (int s = 128; s > 0; s >>= 1) { if (tid < s) red[tid] += red[tid+s]; __syncthreads(); }
    float r = rsqrtf(red[0]*(1.0f/(CIN*9)));
    __syncthreads();
    for (int t = tid; t < CIN*9; t += 256) {
        int i = t/9, kk = t - i*9;
        g_wh[(size_t)o*KTOT + kk*512 + i] = __float2half_rn(wo[t]*r);
    }
    float r2 = r*r;
    float part[BATCH];
#pragma unroll
    for (int b = 0; b < BATCH; b++) part[b] = 0.f;
    for (int i = tid; i < CIN; i += 256) {
        float s9 = 0.f;
#pragma unroll
        for (int k = 0; k < 9; k++) { float v = wo[i*9+k]; s9 += v*v; }
        float w2 = s9*r2;
#pragma unroll
        for (int b = 0; b < BATCH; b++) {
            float sv = g_styles[b*CIN+i];
            part[b] += sv*sv*w2;
        }
    }
#pragma unroll
    for (int b = 0; b < BATCH; b++) {
        red[tid] = part[b]; __syncthreads();
        for (int s = 128; s > 0; s >>= 1) { if (tid < s) red[tid] += red[tid+s]; __syncthreads(); }
        if (tid == 0) g_d[b*COUT+o] = rsqrtf(red[0] + 1e-8f);
        __syncthreads();
    }
}

// ============ K_pad: padded style-scaled fp16 input ============
__global__ void k_pad(const float* __restrict__ x) {
    int idx = blockIdx.x*256 + threadIdx.x;
    if (idx >= BATCH*CIN*XPL) return;
    int col = idx % XPW, row = (idx/XPW) % XPH;
    int c = (idx/XPL) % CIN, b = idx/(XPL*CIN);
    int ri = row - 2, ci = col - 2;
    float v = 0.f;
    if (ri >= 0 && ri < INS && ci >= 0 && ci < INS)
        v = x[(((size_t)b*CIN+c)*INS+ri)*INS+ci] * g_styles[b*CIN+c];
    g_xh[idx] = __float2half_rn(v);
}

// ============ K_gemm: HMMA single-term fp16 implicit conv ============
// SMEM halfs per stage: A[128][40]=5120 | B[32][136]=4352
#define SB_H 5120
#define STGH 9472                      // halfs per stage
#define GEMM_SMEM (2*STGH*2)           // 37888 bytes
#define NCH 144

__global__ __launch_bounds__(256, 2)
void k_gemm(const float* __restrict__ cbias) {
    extern __shared__ __align__(16) char smraw[];
    uint32_t sb = smem_u32(smraw);
    int tid = threadIdx.x, w = tid >> 5, lane = tid & 31;
    int nt = blockIdx.x, oc0 = blockIdx.y * 128, bz = blockIdx.z;
    int wm = w & 1, wn = w >> 1;
    int m0 = wm * 64, n0 = wn * 32;

    // ---- B geometry: warp w loads channels [4w,4w+4) x atoms 0..3 ----
    int pofs[4]; unsigned pv = 0;
#pragma unroll
    for (int t = 0; t < 4; t++) {
        int P, Q;
        if (atom_pix(nt*4 + t, lane, P, Q)) { pofs[t] = P*XPW + Q; pv |= (1u << t); }
        else pofs[t] = 0;
    }

    // ---- A geometry: thread t loads row t>>1, half t&1 (2x CP16) ----
    int arow = tid >> 1, ahalf = tid & 1;

    // ---- ldmatrix base offsets (bytes from stage base) ----
    uint32_t a_base = (uint32_t)(((m0 + (lane & 15))*40 + ((lane >> 4)*8)) * 2);
    uint32_t b_base = (uint32_t)((SB_H + ((lane & 7) + ((lane >> 3) & 1)*8)*136
                                  + n0 + ((lane >> 4)*8)) * 2);

    float acc[64];
#pragma unroll
    for (int t = 0; t < 64; t++) acc[t] = 0.f;

    unsigned short breg[16];

    auto loadA = [&](int ch, int st) {  // cp.async, 16B aligned everywhere
        const __half* src = g_wh + (size_t)(oc0 + arow)*KTOT + ch*32 + ahalf*16;
        uint32_t dst = sb + (uint32_t)((st*STGH + arow*40 + ahalf*16) * 2);
        CP16(dst,      src);
        CP16(dst + 16, src + 8);
    };
    auto ldgB = [&](int ch) {           // coalesced u16 LDG per (channel,atom) row
        int tap = ch >> 4, icb = (ch & 15) << 5;
        int sh = (tap/3)*XPW + (tap - (tap/3)*3);
        const __half* xs = g_xh + (size_t)bz*(CIN*XPL) + (size_t)(icb + w*4)*XPL + sh;
#pragma unroll
        for (int i = 0; i < 16; i++) {
            int k = i >> 2, a = i & 3;   // channel w*4+k, atom a
            breg[i] = ((pv >> a) & 1u)
                ? __ldg((const unsigned short*)xs + (size_t)k*XPL + pofs[a]) : 0;
        }
    };
    auto stsB = [&](int st) {
        uint32_t base = (uint32_t)((st*STGH + SB_H) * 2);
#pragma unroll
        for (int i = 0; i < 16; i++) {
            int k = (w << 2) + (i >> 2), a = i & 3;
            uint32_t idx = (uint32_t)((k*136 + a*32 + lane) * 2);
            *(unsigned short*)(smraw + base + idx) = breg[i];
        }
    };

    // prologue: fill stage 0
    ldgB(0);
    stsB(0);
    loadA(0, 0); CPC();
    asm volatile("cp.async.wait_group 0;");
    __syncthreads();

    for (int ch = 0; ch < NCH; ch++) {
        int st = ch & 1;
        if (ch + 1 < NCH) {
            ldgB(ch + 1);
            loadA(ch + 1, st ^ 1); CPC();
        }

        uint32_t sbase = sb + (uint32_t)(st * STGH * 2);
#pragma unroll
        for (int k16 = 0; k16 < 2; k16++) {
            uint32_t sA = sbase + a_base + k16*32;
            uint32_t sB = sbase + b_base + k16*(16*136*2);
            uint32_t ah[16], bh[8];
#pragma unroll
            for (int mt = 0; mt < 4; mt++) LDSM4(&ah[mt*4], sA + mt*1280);
#pragma unroll
            for (int n2 = 0; n2 < 2; n2++) LDSM4T(&bh[n2*4], sB + n2*32);
#pragma unroll
            for (int mt = 0; mt < 4; mt++)
#pragma unroll
                for (int n = 0; n < 4; n++)
                    MMA(&acc[(mt*4+n)*4], &ah[mt*4],
                        bh[(n>>1)*4 + (n&1)*2], bh[(n>>1)*4 + (n&1)*2 + 1]);
        }

        if (ch + 1 < NCH) {
            asm volatile("cp.async.wait_group 0;");
            stsB(st ^ 1);
        }
        __syncthreads();
    }

    // ---- epilogue: demod + bias, float2 stores ----
#pragma unroll
    for (int mt = 0; mt < 4; mt++) {
        int ocA = oc0 + m0 + mt*16 + (lane >> 2);
        float dmA = g_d[bz*COUT + ocA],     biA = cbias[ocA];
        float dmB = g_d[bz*COUT + ocA + 8], biB = cbias[ocA + 8];
        size_t rowA = ((size_t)(bz*COUT + ocA)) * PLANE;
        size_t rowB = rowA + (size_t)8 * PLANE;
#pragma unroll
        for (int n = 0; n < 4; n++) {
            int nl = n0 + n*8 + (lane & 3)*2;
            int P, Q;
            if (!atom_pix(nt*4 + (nl >> 5), nl & 31, P, Q)) continue;
            int po = P*Y1S + Q;
            float* c = &acc[(mt*4+n)*4];
            *(float2*)(g_y1 + rowA + po) = make_float2(c[0]*dmA + biA, c[1]*dmA + biA);
            *(float2*)(g_y1 + rowB + po) = make_float2(c[2]*dmB + biB, c[3]*dmB + biB);
        }
    }
}

// ============ K4 v2: paired-polyphase fused FIR (fp16 act, stride 140) ======
// smem: vt 9108 f32 (36432B) | act 138x140 f16 (38640B) => 75072B, 3 CTAs/SM
#define K4_VT_BYTES  (9108*4)
#define K4_SMEM      (K4_VT_BYTES + 138*140*2)

__global__ __launch_bounds__(512, 3)
void k4_fir(float* __restrict__ out) {
    int plane = blockIdx.x, tid = threadIdx.x;
    extern __shared__ char sm4[];
    float*  vt  = (float*)sm4;
    __half* act = (__half*)(sm4 + K4_VT_BYTES);
    const float* src = g_y1 + (size_t)plane*PLANE;
    float fl[12];
#pragma unroll
    for (int k = 0; k < 12; k++) fl[k] = g_filter[k];

    // phase 1: vertical up-FIR, paired rows (2m, 2m+1). 69 pairs x 66 cols.
    for (int e = tid; e < 69*Y1S; e += 512) {
        int m = e / Y1S, i = e - m*Y1S;
        float s[6];
#pragma unroll
        for (int j = 0; j < 6; j++) {
            int row = m - 4 + j;
            s[j] = ((unsigned)row < 66u) ? src[row*Y1S + i] : 0.f;
        }
        float ev = s[0]*fl[10] + s[1]*fl[8] + s[2]*fl[6] + s[3]*fl[4] + s[4]*fl[2] + s[5]*fl[0];
        float od = s[0]*fl[11] + s[1]*fl[9] + s[2]*fl[7] + s[3]*fl[5] + s[4]*fl[3] + s[5]*fl[1];
        vt[(2*m)*Y1S + i]   = 4.f*ev;
        vt[(2*m+1)*Y1S + i] = 4.f*od;
    }
    __syncthreads();

    // phase 2: horizontal up-FIR + lrelu + clamp, paired cols. 138 rows x 69 pairs.
    for (int e = tid; e < UPS*69; e += 512) {
        int r = e / 69, m = e - r*69;
        const float* vr = vt + r*Y1S;
        float s[6];
#pragma unroll
        for (int j = 0; j < 6; j++) {
            int c = m - 4 + j;
            s[j] = ((unsigned)c < 66u) ? vr[c] : 0.f;
        }
        float ev = s[0]*fl[10] + s[1]*fl[8] + s[2]*fl[6] + s[3]*fl[4] + s[4]*fl[2] + s[5]*fl[0];
        float od = s[0]*fl[11] + s[1]*fl[9] + s[2]*fl[7] + s[3]*fl[5] + s[4]*fl[3] + s[5]*fl[1];
        ev = (ev >= 0.f ? ev : 0.2f*ev)*1.4142135623730951f;
        od = (od >= 0.f ? od : 0.2f*od)*1.4142135623730951f;
        ev = fminf(fmaxf(ev, -256.f), 256.f);
        od = fminf(fmaxf(od, -256.f), 256.f);
        *(__half2*)(act + r*140 + 2*m) = __floats2half2_rn(ev, od);
    }
    __syncthreads();

    // phase 3: vertical down-FIR (stride-2 rows), half2 col pairs. 64 x 69.
    for (int e = tid; e < OUTS*69; e += 512) {
        int rr = e / 69, jj = e - rr*69;
        const __half2* ap = (const __half2*)(act + (2*rr)*140 + 2*jj);
        float ax = 0.f, ay = 0.f;
#pragma unroll
        for (int t = 0; t < 12; t++) {
            float2 v = __half22float2(ap[t*70]);
            ax += fl[11-t]*v.x;
            ay += fl[11-t]*v.y;
        }
        *(float2*)(vt + rr*UPS + 2*jj) = make_float2(ax, ay);
    }
    __syncthreads();

    // phase 4: horizontal down-FIR (stride 2), paired outputs. 64 x 32.
    float* dst = out + (size_t)plane*(OUTS*OUTS);
    for (int e = tid; e < OUTS*32; e += 512) {
        int rr = e >> 5, p = e & 31;
        const float* dp = vt + rr*UPS + 4*p;
        float d[14];
#pragma unroll
        for (int q = 0; q < 14; q++) d[q] = dp[q];
        float o0 = 0.f, o1 = 0.f;
#pragma unroll
        for (int t = 0; t < 12; t++) {
            o0 += fl[11-t]*d[t];
            o1 += fl[11-t]*d[t+2];
        }
        *(float2*)(dst + rr*OUTS + 2*p) = make_float2(o0, o1);
    }
}

// ============ launch ============
extern "C" void kernel_launch(void* const* d_in, const int* in_sizes, int n_in,
                              void* d_out, int out_size) {
    const float* x  = (const float*)d_in[0];
    const float* w  = (const float*)d_in[1];
    const float* A  = (const float*)d_in[2];
    const float* ab = (const float*)d_in[3];
    const float* cw = (const float*)d_in[4];
    const float* cb = (const float*)d_in[5];
    float* out = (float*)d_out;

    cudaFuncSetAttribute(k_gemm, cudaFuncAttributeMaxDynamicSharedMemorySize, GEMM_SMEM);
    cudaFuncSetAttribute(k4_fir, cudaFuncAttributeMaxDynamicSharedMemorySize, K4_SMEM);

    k0_styles<<<1, 512>>>(w, A, ab);
    k1_wnorm<<<COUT, 256>>>(cw);
    k_pad<<<(BATCH*CIN*XPL + 255)/256, 256>>>(x);
    k_gemm<<<dim3(35, 4, BATCH), 256, GEMM_SMEM>>>(cb);   // launch idx 3
    k4_fir<<<BATCH*COUT, 512, K4_SMEM>>>(out);
}